// round 2
// baseline (speedup 1.0000x reference)
#include <cuda_runtime.h>
#include <math.h>

// Fixed problem shapes:
// feat0 [2,256,200,200] f32, feat1 [2,256,100,100], feat2 [2,256,50,50],
// feat3 [2,256,25,25], boxes [2,256,4] f32 -> out [512,256,7,7] f32.
#define KROIS   512
#define NC      256
#define OUTHW   7
#define NBINS   49
#define TEMP_W  133      // max window width is 131 (level-0 clip, w=512 box); padded
#define WARPS   8        // warps per block, 1 channel each
#define GRPS    (NC / WARPS)   // 32 channel-groups per roi

// Compute one sample coordinate's (lo, hi, frac) exactly like the reference.
__device__ __forceinline__ void prep_coord(float c, int size,
                                           int& lo, int& hi, float& l, float& h)
{
    c = fmaxf(c, 0.0f);
    lo = (int)c;
    if (lo >= size - 1) { lo = size - 1; hi = size - 1; }
    else                { hi = lo + 1; }
    l = c - (float)lo;
    h = 1.0f - l;
}

__global__ void __launch_bounds__(256)
roi_align_sep_kernel(const float* __restrict__ f0,
                     const float* __restrict__ f1,
                     const float* __restrict__ f2,
                     const float* __restrict__ f3,
                     const float* __restrict__ boxes,
                     float* __restrict__ out)
{
    __shared__ float s_temp[WARPS][OUTHW][TEMP_W];
    __shared__ int4   s_yr[OUTHW];   // absolute row indices (lo0, hi0, lo1, hi1)
    __shared__ float4 s_yw[OUTHW];   // y weights        (hy0, ly0, hy1, ly1)
    __shared__ int4   s_xc[OUTHW];   // absolute col indices
    __shared__ float4 s_xw[OUTHW];   // x weights * 0.25
    __shared__ float  s_f[4];        // x1s, y1s, bin_w, bin_h
    __shared__ int    s_i[2];        // level, W

    const int k   = blockIdx.x >> 5;        // roi index (GRPS = 32 groups per roi)
    const int grp = blockIdx.x & (GRPS - 1);
    const int tid = threadIdx.x;

    // ---- phase 1: per-roi scalars (thread 0) ----
    if (tid == 0) {
        const float* bx = boxes + k * 4;
        float x1 = bx[0], y1 = bx[1], x2 = bx[2], y2 = bx[3];

        float area = (x2 - x1) * (y2 - y1);
        float s    = sqrtf(area);
        float lvl  = floorf(4.0f + log2f(s / 224.0f) + 1e-6f);
        lvl = fminf(fmaxf(lvl, 2.0f), 5.0f);
        int level = (int)lvl - 2;

        const float scales[4] = {0.25f, 0.125f, 0.0625f, 0.03125f};
        const int   dims[4]   = {200, 100, 50, 25};
        float sc = scales[level];
        int   W  = dims[level];

        float x1s = x1 * sc, y1s = y1 * sc;
        float x2s = x2 * sc, y2s = y2 * sc;
        float roi_w = fmaxf(x2s - x1s, 1.0f);
        float roi_h = fmaxf(y2s - y1s, 1.0f);

        s_f[0] = x1s;
        s_f[1] = y1s;
        s_f[2] = roi_w / (float)OUTHW;   // bin_w
        s_f[3] = roi_h / (float)OUTHW;   // bin_h
        s_i[0] = level;
        s_i[1] = W;
    }
    __syncthreads();

    const int   level = s_i[0];
    const int   W     = s_i[1];
    const float x1s   = s_f[0];
    const float y1s   = s_f[1];
    const float bin_w = s_f[2];
    const float bin_h = s_f[3];

    // ---- phase 2: per-bin tables (threads 0-6: y, threads 8-14: x) ----
    if (tid < OUTHW) {
        int p = tid;
        float half = bin_h * 0.5f;
        int lo0, hi0, lo1, hi1; float l0, h0, l1, h1;
        float c0 = y1s + (float)p * bin_h + 0.5f * half;
        float c1 = y1s + (float)p * bin_h + 1.5f * half;
        prep_coord(c0, W, lo0, hi0, l0, h0);
        prep_coord(c1, W, lo1, hi1, l1, h1);
        s_yr[p] = make_int4(lo0, hi0, lo1, hi1);
        s_yw[p] = make_float4(h0, l0, h1, l1);
    } else if (tid >= 8 && tid < 8 + OUTHW) {
        int p = tid - 8;
        float half = bin_w * 0.5f;
        int lo0, hi0, lo1, hi1; float l0, h0, l1, h1;
        float c0 = x1s + (float)p * bin_w + 0.5f * half;
        float c1 = x1s + (float)p * bin_w + 1.5f * half;
        prep_coord(c0, W, lo0, hi0, l0, h0);
        prep_coord(c1, W, lo1, hi1, l1, h1);
        s_xc[p] = make_int4(lo0, hi0, lo1, hi1);
        // fold the 1/(SR*SR) = 0.25 into x weights
        s_xw[p] = make_float4(h0 * 0.25f, l0 * 0.25f, h1 * 0.25f, l1 * 0.25f);
    }
    __syncthreads();

    // window extent (x samples are monotone: min lo = pw0/ix0, max hi = pw6/ix1)
    const int x0 = s_xc[0].x;
    const int Ww = s_xc[6].w - x0 + 1;     // <= 131 by level-selection bound

    const int warp = tid >> 5;
    const int lane = tid & 31;
    const int c    = grp * WARPS + warp;   // channel
    const int b    = k >> 8;               // batch

    const float* feat;
    switch (level) {
        case 0:  feat = f0; break;
        case 1:  feat = f1; break;
        case 2:  feat = f2; break;
        default: feat = f3; break;
    }
    const float* __restrict__ base = feat + (size_t)((b * NC + c) * W) * (size_t)W;

    // ---- temp build: temp[ph][x] = sum_{4 rows} yw * f[row, x0+x] ----
    // lane <-> x : fully coalesced global row loads
    for (int xb = 0; xb < Ww; xb += 32) {
        int xr = xb + lane;
        if (xr < Ww) {
            int x = x0 + xr;               // x <= x0+Ww-1 <= W-1 guaranteed
            #pragma unroll
            for (int ph = 0; ph < OUTHW; ph++) {
                int4   r = s_yr[ph];
                float4 w = s_yw[ph];
                float a = w.x * __ldg(base + r.x * W + x)
                        + w.y * __ldg(base + r.y * W + x)
                        + w.z * __ldg(base + r.z * W + x)
                        + w.w * __ldg(base + r.w * W + x);
                s_temp[warp][ph][xr] = a;
            }
        }
    }
    __syncwarp();

    // ---- output: out[ph,pw] = sum_{4 cols} xw * temp[ph][col] ----
    const size_t obase = (size_t)(k * NC + c) * NBINS;
    #pragma unroll
    for (int o = lane; o < NBINS; o += 32) {
        int ph = o / OUTHW;
        int pw = o - ph * OUTHW;
        int4   xc = s_xc[pw];
        float4 xw = s_xw[pw];
        const float* t = s_temp[warp][ph];
        float v = xw.x * t[xc.x - x0] + xw.y * t[xc.y - x0]
                + xw.z * t[xc.z - x0] + xw.w * t[xc.w - x0];
        out[obase + o] = v;
    }
}

extern "C" void kernel_launch(void* const* d_in, const int* in_sizes, int n_in,
                              void* d_out, int out_size)
{
    const float* f0    = (const float*)d_in[0];
    const float* f1    = (const float*)d_in[1];
    const float* f2    = (const float*)d_in[2];
    const float* f3    = (const float*)d_in[3];
    const float* boxes = (const float*)d_in[4];
    float* out = (float*)d_out;

    const int blocks = KROIS * GRPS;   // 512 * 32 = 16384
    roi_align_sep_kernel<<<blocks, 256>>>(f0, f1, f2, f3, boxes, out);
}

// round 3
// speedup vs baseline: 1.5117x; 1.5117x over previous
#include <cuda_runtime.h>
#include <math.h>

// Fixed problem shapes:
// feat0 [2,256,200,200] f32, feat1 [2,256,100,100], feat2 [2,256,50,50],
// feat3 [2,256,25,25], boxes [2,256,4] f32 -> out [512,256,7,7] f32.
#define KROIS   512
#define NC      256
#define OUTHW   7
#define NBINS   49
#define WARPS   8               // warps per block, 1 channel each
#define GRPS    (NC / WARPS)    // 32 channel-groups per roi
#define TSTRIDE 29              // temp row stride (28 cols + 1 pad, bank spread)

__device__ __forceinline__ void prep_coord(float c, int size,
                                           int& lo, int& hi, float& l, float& h)
{
    c = fmaxf(c, 0.0f);
    lo = (int)c;
    if (lo >= size - 1) { lo = size - 1; hi = size - 1; }
    else                { hi = lo + 1; }
    l = c - (float)lo;
    h = 1.0f - l;
}

__global__ void __launch_bounds__(256)
roi_align_corner_kernel(const float* __restrict__ f0,
                        const float* __restrict__ f1,
                        const float* __restrict__ f2,
                        const float* __restrict__ f3,
                        const float* __restrict__ boxes,
                        float* __restrict__ out)
{
    __shared__ float  s_temp[WARPS][OUTHW * TSTRIDE];
    __shared__ int4   s_yoff[OUTHW];   // row offsets premult by W: (lo0*W, hi0*W, lo1*W, hi1*W)
    __shared__ float4 s_yw[OUTHW];     // (hy0, ly0, hy1, ly1)
    __shared__ float  s_f[4];          // x1s, y1s, bin_w, bin_h
    __shared__ int    s_i[2];          // level, W

    const int k   = blockIdx.x >> 5;          // roi
    const int grp = blockIdx.x & (GRPS - 1);
    const int tid = threadIdx.x;

    // ---- per-roi scalars (thread 0) ----
    if (tid == 0) {
        const float* bx = boxes + k * 4;
        float x1 = bx[0], y1 = bx[1], x2 = bx[2], y2 = bx[3];

        float area = (x2 - x1) * (y2 - y1);
        float s    = sqrtf(area);
        float lvl  = floorf(4.0f + log2f(s / 224.0f) + 1e-6f);
        lvl = fminf(fmaxf(lvl, 2.0f), 5.0f);
        int level = (int)lvl - 2;

        const float scales[4] = {0.25f, 0.125f, 0.0625f, 0.03125f};
        const int   dims[4]   = {200, 100, 50, 25};
        float sc = scales[level];
        int   W  = dims[level];

        float x1s = x1 * sc, y1s = y1 * sc;
        float x2s = x2 * sc, y2s = y2 * sc;
        float roi_w = fmaxf(x2s - x1s, 1.0f);
        float roi_h = fmaxf(y2s - y1s, 1.0f);

        s_f[0] = x1s;
        s_f[1] = y1s;
        s_f[2] = roi_w / (float)OUTHW;
        s_f[3] = roi_h / (float)OUTHW;
        s_i[0] = level;
        s_i[1] = W;
    }
    __syncthreads();

    const int   level = s_i[0];
    const int   W     = s_i[1];
    const float x1s   = s_f[0];
    const float y1s   = s_f[1];
    const float bin_w = s_f[2];
    const float bin_h = s_f[3];

    // ---- y tables (threads 0-6) ----
    if (tid < OUTHW) {
        int p = tid;
        float half = bin_h * 0.5f;
        int lo0, hi0, lo1, hi1; float l0, h0, l1, h1;
        prep_coord(y1s + (float)p * bin_h + 0.5f * half, W, lo0, hi0, l0, h0);
        prep_coord(y1s + (float)p * bin_h + 1.5f * half, W, lo1, hi1, l1, h1);
        s_yoff[p] = make_int4(lo0 * W, hi0 * W, lo1 * W, hi1 * W);
        s_yw[p]   = make_float4(h0, l0, h1, l1);
    }
    __syncthreads();

    const int warp = tid >> 5;
    const int lane = tid & 31;
    const int c    = grp * WARPS + warp;
    const int b    = k >> 8;

    // ---- per-lane x corner: j = 4*pw + 2*ix + corner ----
    const int j      = lane;           // lanes 28-31 idle in phase A
    const int si     = j >> 1;         // 0..13
    const int corner = j & 1;
    const int pwj    = si >> 1;
    const int ixj    = si & 1;

    float half_bw = bin_w * 0.5f;
    int xlo, xhi; float xl, xh;
    prep_coord(x1s + (float)pwj * bin_w + ((float)ixj + 0.5f) * half_bw, W,
               xlo, xhi, xl, xh);
    const int   xc = corner ? xhi : xlo;
    const float xw = 0.25f * (corner ? xl : xh);

    const float* feat;
    switch (level) {
        case 0:  feat = f0; break;
        case 1:  feat = f1; break;
        case 2:  feat = f2; break;
        default: feat = f3; break;
    }
    const float* __restrict__ pbase =
        feat + (size_t)((b * NC + c) * W) * (size_t)W + xc;

    // ---- phase A: temp[ph][j] = xw * sum_4rows( yw * f[row, xc] ) ----
    float* __restrict__ tw = s_temp[warp];
    if (j < 28) {
        #pragma unroll
        for (int ph = 0; ph < OUTHW; ph++) {
            int4   ro = s_yoff[ph];
            float4 yw = s_yw[ph];
            float a = yw.x * __ldg(pbase + ro.x)
                    + yw.y * __ldg(pbase + ro.y)
                    + yw.z * __ldg(pbase + ro.z)
                    + yw.w * __ldg(pbase + ro.w);
            tw[ph * TSTRIDE + j] = a * xw;
        }
    }
    __syncwarp();

    // ---- phase B: out[ph][pw] = sum of 4 temp entries ----
    const size_t obase = (size_t)(k * NC + c) * NBINS;
    #pragma unroll
    for (int o = lane; o < NBINS; o += 32) {
        int ph = o / OUTHW;
        int pw = o - ph * OUTHW;
        const float* t = tw + ph * TSTRIDE + pw * 4;
        out[obase + o] = (t[0] + t[1]) + (t[2] + t[3]);
    }
}

extern "C" void kernel_launch(void* const* d_in, const int* in_sizes, int n_in,
                              void* d_out, int out_size)
{
    const float* f0    = (const float*)d_in[0];
    const float* f1    = (const float*)d_in[1];
    const float* f2    = (const float*)d_in[2];
    const float* f3    = (const float*)d_in[3];
    const float* boxes = (const float*)d_in[4];
    float* out = (float*)d_out;

    const int blocks = KROIS * GRPS;   // 16384
    roi_align_corner_kernel<<<blocks, 256>>>(f0, f1, f2, f3, boxes, out);
}